// round 16
// baseline (speedup 1.0000x reference)
#include <cuda_runtime.h>
#include <cuda_fp16.h>
#include <math.h>
#include <cstdint>

// Problem dims
#define N_TOK 65536
#define DIM   256
#define NEXP  4
#define HID   512
#define EMBD  512
#define SLOTS (2 * N_TOK + NEXP * 128)   // 131584 compact rows (128-aligned per expert)

// ---------------- scratch (device globals) -------------------------------------
__device__ __align__(128) __half g_xh[(size_t)N_TOK * DIM];     // fp16 x
__device__ __align__(128) __half g_h[(size_t)SLOTS * HID];      // compact gated hidden (fp16)
__device__ __align__(128) __half g_yh[(size_t)N_TOK * DIM];     // combined y (fp16 RED target)
__device__ __align__(128) __half g_w1t[NEXP * HID * DIM];       // [e][H][D]
__device__ __align__(128) __half g_w2t[NEXP * DIM * HID];       // [e][D][H]
__device__ __align__(128) __half g_wpt[EMBD * DIM];             // [EMB][D]

__device__ int    g_cnt[NEXP];
__device__ int    g_cnt2[NEXP];
__device__ int    g_off[NEXP + 1];
__device__ int2   g_te[N_TOK];
__device__ float2 g_tg[N_TOK];
__device__ int    g_slot_tok[SLOTS];
__device__ float  g_slot_gate[SLOTS];

// ---------------- helpers -------------------------------------------------------
__device__ __forceinline__ uint32_t smem_to_u32(const void* p) {
    uint32_t a;
    asm("{ .reg .u64 t; cvta.to.shared.u64 t, %1; cvt.u32.u64 %0, t; }" : "=r"(a) : "l"(p));
    return a;
}
__device__ __forceinline__ void cp_async16(uint32_t dst, const void* src) {
    asm volatile("cp.async.cg.shared.global [%0], [%1], 16;"
                 :: "r"(dst), "l"(src) : "memory");
}
__device__ __forceinline__ void ldsm_x4(uint32_t& r0, uint32_t& r1, uint32_t& r2,
                                        uint32_t& r3, uint32_t addr) {
    asm volatile("ldmatrix.sync.aligned.m8n8.x4.shared.b16 {%0,%1,%2,%3}, [%4];"
                 : "=r"(r0), "=r"(r1), "=r"(r2), "=r"(r3) : "r"(addr));
}
__device__ __forceinline__ void mma_f16(float c[4], uint32_t a0, uint32_t a1,
                                        uint32_t a2, uint32_t a3,
                                        uint32_t b0, uint32_t b1) {
    asm volatile(
        "mma.sync.aligned.m16n8k16.row.col.f32.f16.f16.f32 "
        "{%0,%1,%2,%3}, {%4,%5,%6,%7}, {%8,%9}, {%0,%1,%2,%3};"
        : "+f"(c[0]), "+f"(c[1]), "+f"(c[2]), "+f"(c[3])
        : "r"(a0), "r"(a1), "r"(a2), "r"(a3), "r"(b0), "r"(b1));
}
__device__ __forceinline__ uint32_t h2raw(__half2 h) {
    return *reinterpret_cast<uint32_t*>(&h);
}
__device__ __forceinline__ void red_add_h2(__half* ptr, float a, float b) {
    __half2 v = __floats2half2_rn(a, b);
    asm volatile("red.global.add.noftz.f16x2 [%0], %1;"
                 :: "l"(ptr), "r"(h2raw(v)) : "memory");
}
// exact gelu via erff (cheap branchless polynomial path)
__device__ __forceinline__ float gelu_fast(float v) {
    return 0.5f * v * (1.0f + erff(v * 0.70710678118654752f));
}
#define SWZ(off) ((off) ^ (((off) >> 3) & 0x70))

// ---------------- fused prep: weight transposes + init (one launch) -----------------
__global__ void prep_kernel(const float* __restrict__ w1,
                            const float* __restrict__ w2,
                            const float* __restrict__ wp,
                            uint4* __restrict__ yh16) {
    int z = blockIdx.z;
    int tx = threadIdx.x, ty = threadIdx.y;  // 32 x 8
    if (z >= 9) {
        int bi = (z - 9) * 128 + blockIdx.y * 16 + blockIdx.x;
        int i = bi * 256 + ty * 32 + tx;
        yh16[i] = make_uint4(0u, 0u, 0u, 0u);
        if (i < SLOTS) { g_slot_tok[i] = 0; g_slot_gate[i] = 0.f; }
        if (i < NEXP)  { g_cnt[i] = 0; g_cnt2[i] = 0; }
        return;
    }
    __shared__ float t[32][33];
    const float* in;
    __half* out;
    int K, N, n0, k0;
    if (z < 4) {
        in = w1 + (size_t)z * DIM * HID; out = g_w1t + (size_t)z * HID * DIM;
        K = DIM; N = HID; n0 = blockIdx.x * 32; k0 = blockIdx.y * 32;
    } else if (z < 8) {
        in = w2 + (size_t)(z - 4) * HID * DIM; out = g_w2t + (size_t)(z - 4) * DIM * HID;
        K = HID; N = DIM; n0 = blockIdx.y * 32; k0 = blockIdx.x * 32;
    } else {
        in = wp; out = g_wpt;
        K = DIM; N = EMBD; n0 = blockIdx.x * 32; k0 = blockIdx.y * 32;
    }
    #pragma unroll
    for (int j = 0; j < 32; j += 8)
        t[ty + j][tx] = in[(size_t)(k0 + ty + j) * N + n0 + tx];
    __syncthreads();
    #pragma unroll
    for (int j = 0; j < 32; j += 8)
        out[(size_t)(n0 + ty + j) * K + k0 + tx] = __float2half_rn(t[tx][ty + j]);
}

// ---------------- gating + counting + fused x->fp16 ---------------------------------
__global__ void gate_assign_kernel(const float* __restrict__ x, const float* __restrict__ wg,
                                   __half* __restrict__ xh) {
    __shared__ float sw[DIM * NEXP];
    __shared__ int bc[NEXP];
    int tid = threadIdx.x;
    for (int i = tid; i < DIM * NEXP; i += blockDim.x) sw[i] = wg[i];
    if (tid < NEXP) bc[tid] = 0;
    __syncthreads();
    int warp = tid >> 5, lane = tid & 31;
    int token = blockIdx.x * (blockDim.x >> 5) + warp;
    const float* xr = x + (size_t)token * DIM;
    __half* xo = xh + (size_t)token * DIM;
    float s0 = 0.f, s1 = 0.f, s2 = 0.f, s3 = 0.f;
    #pragma unroll
    for (int d = lane; d < DIM; d += 32) {
        float xv = xr[d];
        xo[d] = __float2half_rn(xv);
        s0 += xv * sw[d * NEXP + 0];
        s1 += xv * sw[d * NEXP + 1];
        s2 += xv * sw[d * NEXP + 2];
        s3 += xv * sw[d * NEXP + 3];
    }
    #pragma unroll
    for (int o = 16; o > 0; o >>= 1) {
        s0 += __shfl_down_sync(0xffffffffu, s0, o);
        s1 += __shfl_down_sync(0xffffffffu, s1, o);
        s2 += __shfl_down_sync(0xffffffffu, s2, o);
        s3 += __shfl_down_sync(0xffffffffu, s3, o);
    }
    if (lane == 0) {
        float l[NEXP] = {s0, s1, s2, s3};
        int i1 = 0;
        #pragma unroll
        for (int e = 1; e < NEXP; e++) if (l[e] > l[i1]) i1 = e;
        int i2 = -1;
        #pragma unroll
        for (int e = 0; e < NEXP; e++) {
            if (e == i1) continue;
            if (i2 < 0 || l[e] > l[i2]) i2 = e;
        }
        float t = expf(l[i2] - l[i1]);
        float inv = 1.0f / (1.0f + t);
        g_te[token] = make_int2(i1, i2);
        g_tg[token] = make_float2(inv, t * inv);
        atomicAdd(&bc[i1], 1);
        atomicAdd(&bc[i2], 1);
    }
    __syncthreads();
    if (tid < NEXP) atomicAdd(&g_cnt[tid], bc[tid]);
}

// ---------------- placement: hierarchical atomics (warp -> smem -> 1 global/expert) --
__global__ void place_kernel() {
    __shared__ int s_cnt[NEXP];
    __shared__ int s_base[NEXP];
    int tid = threadIdx.x;
    int n = blockIdx.x * blockDim.x + tid;
    int lane = tid & 31;
    if (tid < NEXP) s_cnt[tid] = 0;
    __syncthreads();

    int offv[NEXP + 1];
    int o = 0;
    #pragma unroll
    for (int e = 0; e < NEXP; e++) { offv[e] = o; o += (g_cnt[e] + 127) & ~127; }
    offv[NEXP] = o;
    if (n == 0) {
        #pragma unroll
        for (int e = 0; e <= NEXP; e++) g_off[e] = offv[e];
    }

    int2 te = g_te[n];
    float2 tg = g_tg[n];
    int p1l = 0, p2l = 0;
    unsigned lt = (1u << lane) - 1u;
    #pragma unroll
    for (int e = 0; e < NEXP; e++) {
        unsigned m1 = __ballot_sync(0xffffffffu, te.x == e);
        unsigned m2 = __ballot_sync(0xffffffffu, te.y == e);
        int tot = __popc(m1) + __popc(m2);
        int wb = 0;
        if (lane == 0 && tot) wb = atomicAdd(&s_cnt[e], tot);
        wb = __shfl_sync(0xffffffffu, wb, 0);
        if (te.x == e) p1l = wb + __popc(m1 & lt);
        if (te.y == e) p2l = wb + __popc(m1) + __popc(m2 & lt);
    }
    __syncthreads();
    if (tid < NEXP) s_base[tid] = atomicAdd(&g_cnt2[tid], s_cnt[tid]);
    __syncthreads();

    int p1 = offv[te.x] + s_base[te.x] + p1l;
    int p2 = offv[te.y] + s_base[te.y] + p2l;
    g_slot_tok[p1] = n;  g_slot_gate[p1] = tg.x;
    g_slot_tok[p2] = n;  g_slot_gate[p2] = tg.y;
}

// ---------------- fp16 mma GEMM: CTA 128x256 (512 thr, 16 warps 2x8), warp 64x32 ----
// Same per-warp tile/pipeline as the validated R13 loop; only the CTA packaging
// changes: A tile staged once per 256 output cols (was per 128) -> 25% less staging.
// MODE 0 (sparse GEMM1): A gathered via slot_tok from xh; epi gate*gelu -> fp16 h
// MODE 1 (sparse GEMM2): A = h compact fp16; epi: red.f16x2 -> yh[token]
// MODE 2 (dense proj):   A = yh; epi + bias -> fp32 out
#define BM 128
#define BN 256
#define BK 64
#define NTHREADS 512
#define A_TILE_B (128 * 128)            // 16384 B
#define B_TILE_B (256 * 128)            // 32768 B
#define STAGE_B (A_TILE_B + B_TILE_B)   // 49152 B
#define NSTAGE 3
#define SMEM_BYTES (NSTAGE * STAGE_B)   // 147456 B -> 1 CTA/SM

template <int KDIM, int MODE>
__global__ void __launch_bounds__(NTHREADS, 1) gemm_mma(
    const __half* __restrict__ A,
    const __half* __restrict__ Bt,
    void* __restrict__ Cv, int ldC,
    const float* __restrict__ aux,
    int bt_estride)
{
    extern __shared__ char smc[];
    const uint32_t smem_base = smem_to_u32(smc);

    const int tid = threadIdx.x;
    const int wid = tid >> 5, lane = tid & 31;
    const int gr = lane >> 2, gc = lane & 3;
    const int warpM = wid & 1, warpN = wid >> 1;    // 2 x 8 warps, warp tile 64x32
    const int n0 = blockIdx.x * BN;

    int e = 0;
    const int row_base = blockIdx.y * BM;
    if (MODE == 0 || MODE == 1) {
        if (row_base >= g_off[NEXP]) return;
        e = (row_base >= g_off[1]) + (row_base >= g_off[2]) + (row_base >= g_off[3]);
    }

    constexpr int NCH = KDIM / BK;

    // staging: A 128 rows x 8 chunks (4 thr/row, 2 chunks each);
    //          B 256 rows x 8 chunks (2 thr/row, 4 chunks each)
    const int fa_row = tid >> 2;
    const int fa_cg0 = (tid & 3) * 2;
    const int fb_row = tid >> 1;
    const int fb_cg0 = (tid & 1) * 4;
    const __half* srcA_base;
    if (MODE == 0) {
        int tok = g_slot_tok[row_base + fa_row];
        srcA_base = A + (size_t)tok * KDIM;
    } else {
        srcA_base = A + (size_t)(row_base + fa_row) * KDIM;
    }
    const __half* srcB_base = Bt + (size_t)e * bt_estride + (size_t)(n0 + fb_row) * KDIM;

    const __half* sA0 = srcA_base + fa_cg0 * 8;
    const __half* sB0 = srcB_base + fb_cg0 * 8;

    float acc[4][4][4];
    #pragma unroll
    for (int mi = 0; mi < 4; mi++)
        #pragma unroll
        for (int ni = 0; ni < 4; ni++)
            #pragma unroll
            for (int j = 0; j < 4; j++) acc[mi][ni][j] = 0.f;

    auto issue_stage = [&](int c) {   // call with COMPILE-TIME c only (loop unrolled)
        const uint32_t sb = (uint32_t)((c % NSTAGE) * STAGE_B);
        const int ko = c * BK;
        #pragma unroll
        for (int i = 0; i < 2; i++) {
            uint32_t d = smem_base + sb +
                         (uint32_t)SWZ(fa_row * 128 + (fa_cg0 + i) * 16);
            cp_async16(d, sA0 + ko + i * 8);
        }
        #pragma unroll
        for (int i = 0; i < 4; i++) {
            uint32_t d = smem_base + sb + A_TILE_B +
                         (uint32_t)SWZ(fb_row * 128 + (fb_cg0 + i) * 16);
            cp_async16(d, sB0 + ko + i * 8);
        }
        asm volatile("cp.async.commit_group;" ::: "memory");
    };

    issue_stage(0);
    issue_stage(1);

    const int a_row = warpM * 64 + (lane & 15);
    const int a_kb  = (lane >> 4) * 16;
    const int b_row = warpN * 32 + ((lane >> 4) << 3) + (lane & 7);
    const int b_kb  = ((lane >> 3) & 1) * 16;

    #pragma unroll
    for (int c = 0; c < NCH; c++) {
        if (c == NCH - 1)
            asm volatile("cp.async.wait_group 0;" ::: "memory");
        else
            asm volatile("cp.async.wait_group 1;" ::: "memory");
        __syncthreads();

        if (c + 2 < NCH) issue_stage(c + 2);

        const uint32_t As = smem_base + (uint32_t)((c % NSTAGE) * STAGE_B);
        const uint32_t Bs = As + A_TILE_B;

        #pragma unroll
        for (int ks = 0; ks < BK / 16; ks++) {
            const int kb = ks * 32;
            uint32_t af[4][4], bf[4][2];
            #pragma unroll
            for (int mi = 0; mi < 4; mi++)
                ldsm_x4(af[mi][0], af[mi][1], af[mi][2], af[mi][3],
                        As + SWZ((a_row + mi * 16) * 128 + kb + a_kb));
            #pragma unroll
            for (int bj = 0; bj < 2; bj++)
                ldsm_x4(bf[bj * 2][0], bf[bj * 2][1], bf[bj * 2 + 1][0], bf[bj * 2 + 1][1],
                        Bs + SWZ((b_row + bj * 16) * 128 + kb + b_kb));
            #pragma unroll
            for (int mi = 0; mi < 4; mi++)
                #pragma unroll
                for (int ni = 0; ni < 4; ni++)
                    mma_f16(acc[mi][ni], af[mi][0], af[mi][1], af[mi][2], af[mi][3],
                            bf[ni][0], bf[ni][1]);
        }
    }

    // ---------------- epilogue ----------------
    const int col0 = n0 + warpN * 32 + gc * 2;
    #pragma unroll
    for (int mi = 0; mi < 4; mi++) {
        const int r0 = row_base + warpM * 64 + mi * 16 + gr;
        if (MODE == 0) {
            const float g0 = g_slot_gate[r0];
            const float g1 = g_slot_gate[r0 + 8];
            __half* p0 = (__half*)Cv + (size_t)r0 * ldC + col0;
            __half* p1 = (__half*)Cv + (size_t)(r0 + 8) * ldC + col0;
            #pragma unroll
            for (int ni = 0; ni < 4; ni++) {
                __half2 h0 = __floats2half2_rn(g0 * gelu_fast(acc[mi][ni][0]),
                                               g0 * gelu_fast(acc[mi][ni][1]));
                __half2 h1 = __floats2half2_rn(g1 * gelu_fast(acc[mi][ni][2]),
                                               g1 * gelu_fast(acc[mi][ni][3]));
                *(__half2*)(p0 + ni * 8) = h0;
                *(__half2*)(p1 + ni * 8) = h1;
            }
        } else if (MODE == 1) {
            const int tok0 = g_slot_tok[r0];
            const int tok1 = g_slot_tok[r0 + 8];
            __half* p0 = (__half*)Cv + (size_t)tok0 * ldC + col0;
            __half* p1 = (__half*)Cv + (size_t)tok1 * ldC + col0;
            #pragma unroll
            for (int ni = 0; ni < 4; ni++) {
                red_add_h2(p0 + ni * 8, acc[mi][ni][0], acc[mi][ni][1]);
                red_add_h2(p1 + ni * 8, acc[mi][ni][2], acc[mi][ni][3]);
            }
        } else {
            float* p0 = (float*)Cv + (size_t)r0 * ldC + col0;
            float* p1 = (float*)Cv + (size_t)(r0 + 8) * ldC + col0;
            #pragma unroll
            for (int ni = 0; ni < 4; ni++) {
                float b0 = aux[col0 + ni * 8], b1 = aux[col0 + ni * 8 + 1];
                *(float2*)(p0 + ni * 8) = make_float2(acc[mi][ni][0] + b0,
                                                      acc[mi][ni][1] + b1);
                *(float2*)(p1 + ni * 8) = make_float2(acc[mi][ni][2] + b0,
                                                      acc[mi][ni][3] + b1);
            }
        }
    }
}

// ---------------- launch -------------------------------------------------------------
extern "C" void kernel_launch(void* const* d_in, const int* in_sizes, int n_in,
                              void* d_out, int out_size) {
    const float* x      = (const float*)d_in[0];   // [N, D]
    const float* w_gate = (const float*)d_in[1];   // [D, E]
    const float* w1     = (const float*)d_in[2];   // [E, D, H]
    const float* w2     = (const float*)d_in[3];   // [E, H, D]
    const float* w_proj = (const float*)d_in[4];   // [D, EMB]
    const float* b_proj = (const float*)d_in[5];   // [EMB]
    float* out = (float*)d_out;                    // [N, EMB]

    __half *xh_p, *h_p, *yh_p, *w1t_p, *w2t_p, *wpt_p;
    cudaGetSymbolAddress((void**)&xh_p, g_xh);
    cudaGetSymbolAddress((void**)&h_p, g_h);
    cudaGetSymbolAddress((void**)&yh_p, g_yh);
    cudaGetSymbolAddress((void**)&w1t_p, g_w1t);
    cudaGetSymbolAddress((void**)&w2t_p, g_w2t);
    cudaGetSymbolAddress((void**)&wpt_p, g_wpt);

    cudaFuncSetAttribute(gemm_mma<DIM, 0>, cudaFuncAttributeMaxDynamicSharedMemorySize, SMEM_BYTES);
    cudaFuncSetAttribute(gemm_mma<HID, 1>, cudaFuncAttributeMaxDynamicSharedMemorySize, SMEM_BYTES);
    cudaFuncSetAttribute(gemm_mma<DIM, 2>, cudaFuncAttributeMaxDynamicSharedMemorySize, SMEM_BYTES);

    const int MAX_TILES = SLOTS / BM;   // 1028

    // (1) fused prep: weight transposes + yh zero + slot arrays + counts
    prep_kernel<<<dim3(16, 8, 9 + 64), dim3(32, 8)>>>(w1, w2, w_proj, (uint4*)yh_p);
    // (2) gating + x->fp16
    gate_assign_kernel<<<N_TOK / 8, 256>>>(x, w_gate, xh_p);
    // (3) placement (hierarchical atomics)
    place_kernel<<<N_TOK / 256, 256>>>();

    // (4) GEMM1 sparse: h[slot] = fp16(gate * gelu(x[tok] @ w1[e]))   <- ncu capture
    gemm_mma<DIM, 0><<<dim3(HID / BN, MAX_TILES), NTHREADS, SMEM_BYTES>>>(
        xh_p, w1t_p, h_p, HID, nullptr, HID * DIM);

    // (5) GEMM2 sparse: yh[tok] += fp16(h[slot] @ w2[e]^T)   (f16x2 RED)
    gemm_mma<HID, 1><<<dim3(DIM / BN, MAX_TILES), NTHREADS, SMEM_BYTES>>>(
        h_p, w2t_p, yh_p, DIM, nullptr, DIM * HID);

    // (6) proj: out = yh @ w_proj + b
    gemm_mma<DIM, 2><<<dim3(EMBD / BN, N_TOK / BM), NTHREADS, SMEM_BYTES>>>(
        yh_p, wpt_p, out, EMBD, b_proj, 0);
}

// round 17
// speedup vs baseline: 1.0521x; 1.0521x over previous
#include <cuda_runtime.h>
#include <cuda_fp16.h>
#include <math.h>
#include <cstdint>

// Problem dims
#define N_TOK 65536
#define DIM   256
#define NEXP  4
#define HID   512
#define EMBD  512
#define SLOTS (2 * N_TOK + NEXP * 128)   // 131584 compact rows (128-aligned per expert)

// ---------------- scratch (device globals) -------------------------------------
__device__ __align__(128) __half g_xh[(size_t)N_TOK * DIM];     // fp16 x
__device__ __align__(128) __half g_h[(size_t)SLOTS * HID];      // compact gated hidden (fp16)
__device__ __align__(128) __half g_yh[(size_t)N_TOK * DIM];     // combined y (fp16 RED target)
__device__ __align__(128) __half g_w1t[NEXP * HID * DIM];       // [e][H][D]
__device__ __align__(128) __half g_w2t[NEXP * DIM * HID];       // [e][D][H]
__device__ __align__(128) __half g_wpt[EMBD * DIM];             // [EMB][D]

__device__ int    g_cnt[NEXP];
__device__ int    g_cnt2[NEXP];
__device__ int    g_off[NEXP + 1];
__device__ int2   g_te[N_TOK];
__device__ float2 g_tg[N_TOK];
__device__ int    g_slot_tok[SLOTS];
__device__ float  g_slot_gate[SLOTS];

// ---------------- helpers -------------------------------------------------------
__device__ __forceinline__ uint32_t smem_to_u32(const void* p) {
    uint32_t a;
    asm("{ .reg .u64 t; cvta.to.shared.u64 t, %1; cvt.u32.u64 %0, t; }" : "=r"(a) : "l"(p));
    return a;
}
__device__ __forceinline__ void cp_async16(uint32_t dst, const void* src) {
    asm volatile("cp.async.cg.shared.global [%0], [%1], 16;"
                 :: "r"(dst), "l"(src) : "memory");
}
__device__ __forceinline__ void ldsm_x4(uint32_t& r0, uint32_t& r1, uint32_t& r2,
                                        uint32_t& r3, uint32_t addr) {
    asm volatile("ldmatrix.sync.aligned.m8n8.x4.shared.b16 {%0,%1,%2,%3}, [%4];"
                 : "=r"(r0), "=r"(r1), "=r"(r2), "=r"(r3) : "r"(addr));
}
__device__ __forceinline__ void mma_f16(float c[4], uint32_t a0, uint32_t a1,
                                        uint32_t a2, uint32_t a3,
                                        uint32_t b0, uint32_t b1) {
    asm volatile(
        "mma.sync.aligned.m16n8k16.row.col.f32.f16.f16.f32 "
        "{%0,%1,%2,%3}, {%4,%5,%6,%7}, {%8,%9}, {%0,%1,%2,%3};"
        : "+f"(c[0]), "+f"(c[1]), "+f"(c[2]), "+f"(c[3])
        : "r"(a0), "r"(a1), "r"(a2), "r"(a3), "r"(b0), "r"(b1));
}
__device__ __forceinline__ uint32_t h2raw(__half2 h) {
    return *reinterpret_cast<uint32_t*>(&h);
}
__device__ __forceinline__ void red_add_h2(__half* ptr, float a, float b) {
    __half2 v = __floats2half2_rn(a, b);
    asm volatile("red.global.add.noftz.f16x2 [%0], %1;"
                 :: "l"(ptr), "r"(h2raw(v)) : "memory");
}
// exact gelu via erff (cheap branchless polynomial path)
__device__ __forceinline__ float gelu_fast(float v) {
    return 0.5f * v * (1.0f + erff(v * 0.70710678118654752f));
}
#define SWZ(off) ((off) ^ (((off) >> 3) & 0x70))

// ---------------- fused prep: weight transposes + init (one launch) -----------------
__global__ void prep_kernel(const float* __restrict__ w1,
                            const float* __restrict__ w2,
                            const float* __restrict__ wp,
                            uint4* __restrict__ yh16) {
    int z = blockIdx.z;
    int tx = threadIdx.x, ty = threadIdx.y;  // 32 x 8
    if (z >= 9) {
        int bi = (z - 9) * 128 + blockIdx.y * 16 + blockIdx.x;
        int i = bi * 256 + ty * 32 + tx;
        yh16[i] = make_uint4(0u, 0u, 0u, 0u);
        if (i < SLOTS) { g_slot_tok[i] = 0; g_slot_gate[i] = 0.f; }
        if (i < NEXP)  { g_cnt[i] = 0; g_cnt2[i] = 0; }
        return;
    }
    __shared__ float t[32][33];
    const float* in;
    __half* out;
    int K, N, n0, k0;
    if (z < 4) {
        in = w1 + (size_t)z * DIM * HID; out = g_w1t + (size_t)z * HID * DIM;
        K = DIM; N = HID; n0 = blockIdx.x * 32; k0 = blockIdx.y * 32;
    } else if (z < 8) {
        in = w2 + (size_t)(z - 4) * HID * DIM; out = g_w2t + (size_t)(z - 4) * DIM * HID;
        K = HID; N = DIM; n0 = blockIdx.y * 32; k0 = blockIdx.x * 32;
    } else {
        in = wp; out = g_wpt;
        K = DIM; N = EMBD; n0 = blockIdx.x * 32; k0 = blockIdx.y * 32;
    }
    #pragma unroll
    for (int j = 0; j < 32; j += 8)
        t[ty + j][tx] = in[(size_t)(k0 + ty + j) * N + n0 + tx];
    __syncthreads();
    #pragma unroll
    for (int j = 0; j < 32; j += 8)
        out[(size_t)(n0 + ty + j) * K + k0 + tx] = __float2half_rn(t[tx][ty + j]);
}

// ---------------- gating + counting + fused x->fp16 ---------------------------------
__global__ void gate_assign_kernel(const float* __restrict__ x, const float* __restrict__ wg,
                                   __half* __restrict__ xh) {
    __shared__ float sw[DIM * NEXP];
    __shared__ int bc[NEXP];
    int tid = threadIdx.x;
    for (int i = tid; i < DIM * NEXP; i += blockDim.x) sw[i] = wg[i];
    if (tid < NEXP) bc[tid] = 0;
    __syncthreads();
    int warp = tid >> 5, lane = tid & 31;
    int token = blockIdx.x * (blockDim.x >> 5) + warp;
    const float* xr = x + (size_t)token * DIM;
    __half* xo = xh + (size_t)token * DIM;
    float s0 = 0.f, s1 = 0.f, s2 = 0.f, s3 = 0.f;
    #pragma unroll
    for (int d = lane; d < DIM; d += 32) {
        float xv = xr[d];
        xo[d] = __float2half_rn(xv);
        s0 += xv * sw[d * NEXP + 0];
        s1 += xv * sw[d * NEXP + 1];
        s2 += xv * sw[d * NEXP + 2];
        s3 += xv * sw[d * NEXP + 3];
    }
    #pragma unroll
    for (int o = 16; o > 0; o >>= 1) {
        s0 += __shfl_down_sync(0xffffffffu, s0, o);
        s1 += __shfl_down_sync(0xffffffffu, s1, o);
        s2 += __shfl_down_sync(0xffffffffu, s2, o);
        s3 += __shfl_down_sync(0xffffffffu, s3, o);
    }
    if (lane == 0) {
        float l[NEXP] = {s0, s1, s2, s3};
        int i1 = 0;
        #pragma unroll
        for (int e = 1; e < NEXP; e++) if (l[e] > l[i1]) i1 = e;
        int i2 = -1;
        #pragma unroll
        for (int e = 0; e < NEXP; e++) {
            if (e == i1) continue;
            if (i2 < 0 || l[e] > l[i2]) i2 = e;
        }
        float t = expf(l[i2] - l[i1]);
        float inv = 1.0f / (1.0f + t);
        g_te[token] = make_int2(i1, i2);
        g_tg[token] = make_float2(inv, t * inv);
        atomicAdd(&bc[i1], 1);
        atomicAdd(&bc[i2], 1);
    }
    __syncthreads();
    if (tid < NEXP) atomicAdd(&g_cnt[tid], bc[tid]);
}

// ---------------- placement: hierarchical atomics (warp -> smem -> 1 global/expert) --
__global__ void place_kernel() {
    __shared__ int s_cnt[NEXP];
    __shared__ int s_base[NEXP];
    int tid = threadIdx.x;
    int n = blockIdx.x * blockDim.x + tid;
    int lane = tid & 31;
    if (tid < NEXP) s_cnt[tid] = 0;
    __syncthreads();

    int offv[NEXP + 1];
    int o = 0;
    #pragma unroll
    for (int e = 0; e < NEXP; e++) { offv[e] = o; o += (g_cnt[e] + 127) & ~127; }
    offv[NEXP] = o;
    if (n == 0) {
        #pragma unroll
        for (int e = 0; e <= NEXP; e++) g_off[e] = offv[e];
    }

    int2 te = g_te[n];
    float2 tg = g_tg[n];
    int p1l = 0, p2l = 0;
    unsigned lt = (1u << lane) - 1u;
    #pragma unroll
    for (int e = 0; e < NEXP; e++) {
        unsigned m1 = __ballot_sync(0xffffffffu, te.x == e);
        unsigned m2 = __ballot_sync(0xffffffffu, te.y == e);
        int tot = __popc(m1) + __popc(m2);
        int wb = 0;
        if (lane == 0 && tot) wb = atomicAdd(&s_cnt[e], tot);
        wb = __shfl_sync(0xffffffffu, wb, 0);
        if (te.x == e) p1l = wb + __popc(m1 & lt);
        if (te.y == e) p2l = wb + __popc(m1) + __popc(m2 & lt);
    }
    __syncthreads();
    if (tid < NEXP) s_base[tid] = atomicAdd(&g_cnt2[tid], s_cnt[tid]);
    __syncthreads();

    int p1 = offv[te.x] + s_base[te.x] + p1l;
    int p2 = offv[te.y] + s_base[te.y] + p2l;
    g_slot_tok[p1] = n;  g_slot_gate[p1] = tg.x;
    g_slot_tok[p2] = n;  g_slot_gate[p2] = tg.y;
}

// ---------------- fp16 mma GEMM, 256-thr CTA 128x128 (R15 geometry) -----------------
// MODE 0 (sparse GEMM1): A gathered via slot_tok from xh; epi gate*gelu -> fp16 h
// MODE 2 (dense proj):   A = yh; epi + bias -> fp32 out
#define BM 128
#define BN 128
#define BK 64
#define TILE_B (128 * 128)
#define STAGE_B (2 * TILE_B)
#define NSTAGE 3
#define SMEM_BYTES (NSTAGE * STAGE_B)   // 98304

template <int KDIM, int MODE>
__global__ void __launch_bounds__(256, 2) gemm_mma(
    const __half* __restrict__ A,
    const __half* __restrict__ Bt,
    void* __restrict__ Cv, int ldC,
    const float* __restrict__ aux,
    int bt_estride)
{
    extern __shared__ char smc[];
    const uint32_t smem_base = smem_to_u32(smc);

    const int tid = threadIdx.x;
    const int wid = tid >> 5, lane = tid & 31;
    const int gr = lane >> 2, gc = lane & 3;
    const int warpM = wid >> 2, warpN = wid & 3;
    const int n0 = blockIdx.x * BN;

    int e = 0;
    const int row_base = blockIdx.y * BM;
    if (MODE == 0 || MODE == 1) {
        if (row_base >= g_off[NEXP]) return;
        e = (row_base >= g_off[1]) + (row_base >= g_off[2]) + (row_base >= g_off[3]);
    }

    constexpr int NCH = KDIM / BK;

    const int f_row = tid >> 1;
    const int f_cg0 = (tid & 1) * 4;
    const __half* srcA_base;
    if (MODE == 0) {
        int tok = g_slot_tok[row_base + f_row];
        srcA_base = A + (size_t)tok * KDIM;
    } else {
        srcA_base = A + (size_t)(row_base + f_row) * KDIM;
    }
    const __half* srcB_base = Bt + (size_t)e * bt_estride + (size_t)(n0 + f_row) * KDIM;

    const __half* sA0 = srcA_base + f_cg0 * 8;
    const __half* sB0 = srcB_base + f_cg0 * 8;

    float acc[4][4][4];
    #pragma unroll
    for (int mi = 0; mi < 4; mi++)
        #pragma unroll
        for (int ni = 0; ni < 4; ni++)
            #pragma unroll
            for (int j = 0; j < 4; j++) acc[mi][ni][j] = 0.f;

    auto issue_stage = [&](int c) {   // call with COMPILE-TIME c only (loop unrolled)
        const uint32_t sb = (uint32_t)((c % NSTAGE) * STAGE_B);
        const int ko = c * BK;
        #pragma unroll
        for (int i = 0; i < 4; i++) {
            uint32_t d = smem_base + sb +
                         (uint32_t)SWZ(f_row * 128 + (f_cg0 + i) * 16);
            cp_async16(d, sA0 + ko + i * 8);
        }
        #pragma unroll
        for (int i = 0; i < 4; i++) {
            uint32_t d = smem_base + sb + TILE_B +
                         (uint32_t)SWZ(f_row * 128 + (f_cg0 + i) * 16);
            cp_async16(d, sB0 + ko + i * 8);
        }
        asm volatile("cp.async.commit_group;" ::: "memory");
    };

    issue_stage(0);
    issue_stage(1);

    const int a_row = warpM * 64 + (lane & 15);
    const int a_kb  = (lane >> 4) * 16;
    const int b_row = warpN * 32 + ((lane >> 4) << 3) + (lane & 7);
    const int b_kb  = ((lane >> 3) & 1) * 16;

    #pragma unroll
    for (int c = 0; c < NCH; c++) {
        if (c == NCH - 1)
            asm volatile("cp.async.wait_group 0;" ::: "memory");
        else
            asm volatile("cp.async.wait_group 1;" ::: "memory");
        __syncthreads();

        if (c + 2 < NCH) issue_stage(c + 2);

        const uint32_t As = smem_base + (uint32_t)((c % NSTAGE) * STAGE_B);
        const uint32_t Bs = As + TILE_B;

        #pragma unroll
        for (int ks = 0; ks < BK / 16; ks++) {
            const int kb = ks * 32;
            uint32_t af[4][4], bf[4][2];
            #pragma unroll
            for (int mi = 0; mi < 4; mi++)
                ldsm_x4(af[mi][0], af[mi][1], af[mi][2], af[mi][3],
                        As + SWZ((a_row + mi * 16) * 128 + kb + a_kb));
            #pragma unroll
            for (int bj = 0; bj < 2; bj++)
                ldsm_x4(bf[bj * 2][0], bf[bj * 2][1], bf[bj * 2 + 1][0], bf[bj * 2 + 1][1],
                        Bs + SWZ((b_row + bj * 16) * 128 + kb + b_kb));
            #pragma unroll
            for (int mi = 0; mi < 4; mi++)
                #pragma unroll
                for (int ni = 0; ni < 4; ni++)
                    mma_f16(acc[mi][ni], af[mi][0], af[mi][1], af[mi][2], af[mi][3],
                            bf[ni][0], bf[ni][1]);
        }
    }

    // ---------------- epilogue ----------------
    const int col0 = n0 + warpN * 32 + gc * 2;
    #pragma unroll
    for (int mi = 0; mi < 4; mi++) {
        const int r0 = row_base + warpM * 64 + mi * 16 + gr;
        if (MODE == 0) {
            const float g0 = g_slot_gate[r0];
            const float g1 = g_slot_gate[r0 + 8];
            __half* p0 = (__half*)Cv + (size_t)r0 * ldC + col0;
            __half* p1 = (__half*)Cv + (size_t)(r0 + 8) * ldC + col0;
            #pragma unroll
            for (int ni = 0; ni < 4; ni++) {
                __half2 h0 = __floats2half2_rn(g0 * gelu_fast(acc[mi][ni][0]),
                                               g0 * gelu_fast(acc[mi][ni][1]));
                __half2 h1 = __floats2half2_rn(g1 * gelu_fast(acc[mi][ni][2]),
                                               g1 * gelu_fast(acc[mi][ni][3]));
                *(__half2*)(p0 + ni * 8) = h0;
                *(__half2*)(p1 + ni * 8) = h1;
            }
        } else if (MODE == 1) {
            const int tok0 = g_slot_tok[r0];
            const int tok1 = g_slot_tok[r0 + 8];
            __half* p0 = (__half*)Cv + (size_t)tok0 * ldC + col0;
            __half* p1 = (__half*)Cv + (size_t)tok1 * ldC + col0;
            #pragma unroll
            for (int ni = 0; ni < 4; ni++) {
                red_add_h2(p0 + ni * 8, acc[mi][ni][0], acc[mi][ni][1]);
                red_add_h2(p1 + ni * 8, acc[mi][ni][2], acc[mi][ni][3]);
            }
        } else {
            float* p0 = (float*)Cv + (size_t)r0 * ldC + col0;
            float* p1 = (float*)Cv + (size_t)(r0 + 8) * ldC + col0;
            #pragma unroll
            for (int ni = 0; ni < 4; ni++) {
                float b0 = aux[col0 + ni * 8], b1 = aux[col0 + ni * 8 + 1];
                *(float2*)(p0 + ni * 8) = make_float2(acc[mi][ni][0] + b0,
                                                      acc[mi][ni][1] + b1);
                *(float2*)(p1 + ni * 8) = make_float2(acc[mi][ni][2] + b0,
                                                      acc[mi][ni][3] + b1);
            }
        }
    }
}

// ---------------- wide variant for GEMM2 only: 512 thr, BN=256, 1 n-tile -------------
// Halves DRAM reads of h (128 MB operand, larger than L2): A staged exactly once.
#define WBN 256
#define WA_TILE_B (128 * 128)             // 16384 B
#define WB_TILE_B (256 * 128)             // 32768 B
#define WSTAGE_B (WA_TILE_B + WB_TILE_B)  // 49152 B
#define WSMEM_BYTES (NSTAGE * WSTAGE_B)   // 147456 B -> 1 CTA/SM

template <int KDIM>
__global__ void __launch_bounds__(512, 1) gemm_mma_wide(
    const __half* __restrict__ A,
    const __half* __restrict__ Bt,
    __half* __restrict__ Yh, int ldC,
    int bt_estride)
{
    extern __shared__ char smc[];
    const uint32_t smem_base = smem_to_u32(smc);

    const int tid = threadIdx.x;
    const int wid = tid >> 5, lane = tid & 31;
    const int gr = lane >> 2, gc = lane & 3;
    const int warpM = wid & 1, warpN = wid >> 1;    // 2 x 8 warps, warp tile 64x32
    const int n0 = 0;                               // grid.x == 1

    const int row_base = blockIdx.y * BM;
    if (row_base >= g_off[NEXP]) return;
    const int e = (row_base >= g_off[1]) + (row_base >= g_off[2]) + (row_base >= g_off[3]);

    constexpr int NCH = KDIM / BK;

    const int fa_row = tid >> 2;
    const int fa_cg0 = (tid & 3) * 2;
    const int fb_row = tid >> 1;
    const int fb_cg0 = (tid & 1) * 4;
    const __half* srcA_base = A + (size_t)(row_base + fa_row) * KDIM;
    const __half* srcB_base = Bt + (size_t)e * bt_estride + (size_t)(n0 + fb_row) * KDIM;

    const __half* sA0 = srcA_base + fa_cg0 * 8;
    const __half* sB0 = srcB_base + fb_cg0 * 8;

    float acc[4][4][4];
    #pragma unroll
    for (int mi = 0; mi < 4; mi++)
        #pragma unroll
        for (int ni = 0; ni < 4; ni++)
            #pragma unroll
            for (int j = 0; j < 4; j++) acc[mi][ni][j] = 0.f;

    auto issue_stage = [&](int c) {   // COMPILE-TIME c only
        const uint32_t sb = (uint32_t)((c % NSTAGE) * WSTAGE_B);
        const int ko = c * BK;
        #pragma unroll
        for (int i = 0; i < 2; i++) {
            uint32_t d = smem_base + sb +
                         (uint32_t)SWZ(fa_row * 128 + (fa_cg0 + i) * 16);
            cp_async16(d, sA0 + ko + i * 8);
        }
        #pragma unroll
        for (int i = 0; i < 4; i++) {
            uint32_t d = smem_base + sb + WA_TILE_B +
                         (uint32_t)SWZ(fb_row * 128 + (fb_cg0 + i) * 16);
            cp_async16(d, sB0 + ko + i * 8);
        }
        asm volatile("cp.async.commit_group;" ::: "memory");
    };

    issue_stage(0);
    issue_stage(1);

    const int a_row = warpM * 64 + (lane & 15);
    const int a_kb  = (lane >> 4) * 16;
    const int b_row = warpN * 32 + ((lane >> 4) << 3) + (lane & 7);
    const int b_kb  = ((lane >> 3) & 1) * 16;

    #pragma unroll
    for (int c = 0; c < NCH; c++) {
        if (c == NCH - 1)
            asm volatile("cp.async.wait_group 0;" ::: "memory");
        else
            asm volatile("cp.async.wait_group 1;" ::: "memory");
        __syncthreads();

        if (c + 2 < NCH) issue_stage(c + 2);

        const uint32_t As = smem_base + (uint32_t)((c % NSTAGE) * WSTAGE_B);
        const uint32_t Bs = As + WA_TILE_B;

        #pragma unroll
        for (int ks = 0; ks < BK / 16; ks++) {
            const int kb = ks * 32;
            uint32_t af[4][4], bf[4][2];
            #pragma unroll
            for (int mi = 0; mi < 4; mi++)
                ldsm_x4(af[mi][0], af[mi][1], af[mi][2], af[mi][3],
                        As + SWZ((a_row + mi * 16) * 128 + kb + a_kb));
            #pragma unroll
            for (int bj = 0; bj < 2; bj++)
                ldsm_x4(bf[bj * 2][0], bf[bj * 2][1], bf[bj * 2 + 1][0], bf[bj * 2 + 1][1],
                        Bs + SWZ((b_row + bj * 16) * 128 + kb + b_kb));
            #pragma unroll
            for (int mi = 0; mi < 4; mi++)
                #pragma unroll
                for (int ni = 0; ni < 4; ni++)
                    mma_f16(acc[mi][ni], af[mi][0], af[mi][1], af[mi][2], af[mi][3],
                            bf[ni][0], bf[ni][1]);
        }
    }

    // ---------------- epilogue: f16x2 RED into yh[token] ----------------
    const int col0 = n0 + warpN * 32 + gc * 2;
    #pragma unroll
    for (int mi = 0; mi < 4; mi++) {
        const int r0 = row_base + warpM * 64 + mi * 16 + gr;
        const int tok0 = g_slot_tok[r0];
        const int tok1 = g_slot_tok[r0 + 8];
        __half* p0 = Yh + (size_t)tok0 * ldC + col0;
        __half* p1 = Yh + (size_t)tok1 * ldC + col0;
        #pragma unroll
        for (int ni = 0; ni < 4; ni++) {
            red_add_h2(p0 + ni * 8, acc[mi][ni][0], acc[mi][ni][1]);
            red_add_h2(p1 + ni * 8, acc[mi][ni][2], acc[mi][ni][3]);
        }
    }
}

// ---------------- launch -------------------------------------------------------------
extern "C" void kernel_launch(void* const* d_in, const int* in_sizes, int n_in,
                              void* d_out, int out_size) {
    const float* x      = (const float*)d_in[0];   // [N, D]
    const float* w_gate = (const float*)d_in[1];   // [D, E]
    const float* w1     = (const float*)d_in[2];   // [E, D, H]
    const float* w2     = (const float*)d_in[3];   // [E, H, D]
    const float* w_proj = (const float*)d_in[4];   // [D, EMB]
    const float* b_proj = (const float*)d_in[5];   // [EMB]
    float* out = (float*)d_out;                    // [N, EMB]

    __half *xh_p, *h_p, *yh_p, *w1t_p, *w2t_p, *wpt_p;
    cudaGetSymbolAddress((void**)&xh_p, g_xh);
    cudaGetSymbolAddress((void**)&h_p, g_h);
    cudaGetSymbolAddress((void**)&yh_p, g_yh);
    cudaGetSymbolAddress((void**)&w1t_p, g_w1t);
    cudaGetSymbolAddress((void**)&w2t_p, g_w2t);
    cudaGetSymbolAddress((void**)&wpt_p, g_wpt);

    cudaFuncSetAttribute(gemm_mma<DIM, 0>, cudaFuncAttributeMaxDynamicSharedMemorySize, SMEM_BYTES);
    cudaFuncSetAttribute(gemm_mma<DIM, 2>, cudaFuncAttributeMaxDynamicSharedMemorySize, SMEM_BYTES);
    cudaFuncSetAttribute(gemm_mma_wide<HID>, cudaFuncAttributeMaxDynamicSharedMemorySize, WSMEM_BYTES);

    const int MAX_TILES = SLOTS / BM;   // 1028

    // (1) fused prep: weight transposes + yh zero + slot arrays + counts
    prep_kernel<<<dim3(16, 8, 9 + 64), dim3(32, 8)>>>(w1, w2, w_proj, (uint4*)yh_p);
    // (2) gating + x->fp16
    gate_assign_kernel<<<N_TOK / 8, 256>>>(x, w_gate, xh_p);
    // (3) placement (hierarchical atomics)
    place_kernel<<<N_TOK / 256, 256>>>();

    // (4) GEMM1 sparse: h[slot] = fp16(gate * gelu(x[tok] @ w1[e]))   <- ncu capture
    gemm_mma<DIM, 0><<<dim3(HID / BN, MAX_TILES), 256, SMEM_BYTES>>>(
        xh_p, w1t_p, h_p, HID, nullptr, HID * DIM);

    // (5) GEMM2 sparse (wide, BN=256, 1 n-tile -> h read once):
    //     yh[tok] += fp16(h[slot] @ w2[e]^T)
    gemm_mma_wide<HID><<<dim3(1, MAX_TILES), 512, WSMEM_BYTES>>>(
        h_p, w2t_p, yh_p, DIM, DIM * HID);

    // (6) proj: out = yh @ w_proj + b
    gemm_mma<DIM, 2><<<dim3(EMBD / BN, N_TOK / BM), 256, SMEM_BYTES>>>(
        yh_p, wpt_p, out, EMBD, b_proj, 0);
}